// round 1
// baseline (speedup 1.0000x reference)
#include <cuda_runtime.h>
#include <math.h>

// Problem constants
#define T   2048
#define Dm  512
#define H   8
#define DH  64
#define CH  128          // chunk length
#define NC  (T / CH)     // 16 chunks
#define STATS_STRIDE (DH*DH + DH)  // 4160 floats per (head,chunk): [KV 64x64 | ksum 64]

// Scratch (device globals — no allocation allowed)
__device__ float g_Qp[H * T * DH];
__device__ float g_Kp[H * T * DH];
__device__ float g_V [H * T * DH];
__device__ float g_stats[H * NC * STATS_STRIDE];
__device__ float g_pref [H * NC * STATS_STRIDE];
__device__ float g_O [T * Dm];

// ---------------------------------------------------------------------------
// Kernel 1: fused QKV projection  (x[2048,512] @ W[512,512] + b), epilogue:
//   Q,K -> elu(x)+1 ;  V -> identity.  Output layout: [h][t][d] head-major.
// 64x64 tile, BK=16, 256 threads, 4x4 microtile.
// grid = (T/64, 8, 3)   blockIdx.y == head (tiles are head-aligned)
// ---------------------------------------------------------------------------
__global__ void qkv_kernel(const float* __restrict__ x,
                           const float* __restrict__ Wq, const float* __restrict__ bq,
                           const float* __restrict__ Wk, const float* __restrict__ bk,
                           const float* __restrict__ Wv, const float* __restrict__ bv)
{
    __shared__ float As[64 * 16];
    __shared__ float Bs[16 * 64];

    const int which = blockIdx.z;
    const float* W = (which == 0) ? Wq : (which == 1) ? Wk : Wv;
    const float* b = (which == 0) ? bq : (which == 1) ? bk : bv;
    float* out = (which == 0) ? g_Qp : (which == 1) ? g_Kp : g_V;

    const int row0 = blockIdx.x * 64;
    const int col0 = blockIdx.y * 64;
    const int tid = threadIdx.x;
    const int tx = tid & 15, ty = tid >> 4;

    float acc[4][4];
    #pragma unroll
    for (int i = 0; i < 4; i++)
        #pragma unroll
        for (int j = 0; j < 4; j++) acc[i][j] = 0.f;

    for (int k0 = 0; k0 < Dm; k0 += 16) {
        #pragma unroll
        for (int i = 0; i < 4; i++) {            // A tile 64x16
            int idx = tid + i * 256;
            int r = idx >> 4, c = idx & 15;
            As[r * 16 + c] = x[(row0 + r) * Dm + k0 + c];
        }
        #pragma unroll
        for (int i = 0; i < 4; i++) {            // B tile 16x64
            int idx = tid + i * 256;
            int r = idx >> 6, c = idx & 63;
            Bs[r * 64 + c] = W[(k0 + r) * Dm + col0 + c];
        }
        __syncthreads();
        #pragma unroll
        for (int k = 0; k < 16; k++) {
            float a[4], bb[4];
            #pragma unroll
            for (int i = 0; i < 4; i++) a[i] = As[(ty * 4 + i) * 16 + k];
            #pragma unroll
            for (int j = 0; j < 4; j++) bb[j] = Bs[k * 64 + tx * 4 + j];
            #pragma unroll
            for (int i = 0; i < 4; i++)
                #pragma unroll
                for (int j = 0; j < 4; j++) acc[i][j] += a[i] * bb[j];
        }
        __syncthreads();
    }

    const int h = blockIdx.y;          // 64-wide tiles == heads
    #pragma unroll
    for (int i = 0; i < 4; i++) {
        int t = row0 + ty * 4 + i;
        #pragma unroll
        for (int j = 0; j < 4; j++) {
            int d = tx * 4 + j;
            float v = acc[i][j] + b[col0 + d];
            if (which < 2) v = (v > 0.f) ? (v + 1.f) : expf(v);  // elu(x)+1
            out[((h * T + t) << 6) + d] = v;
        }
    }
}

// ---------------------------------------------------------------------------
// Kernel 2: per-(head,chunk) stats: KV = Kp_chunk^T @ V_chunk (64x64),
//           ksum = sum over chunk of Kp (64).
// grid = (NC, H), 256 threads. Streams chunk in 4 slices of 32 rows.
// ---------------------------------------------------------------------------
__global__ void chunk_kernel()
{
    __shared__ float Ks[32 * 65];
    __shared__ float Vs[32 * 65];

    const int c = blockIdx.x, h = blockIdx.y;
    const int tid = threadIdx.x;
    const int tx = tid & 15, ty = tid >> 4;

    const float* Kbase = g_Kp + ((h * T + c * CH) << 6);
    const float* Vbase = g_V  + ((h * T + c * CH) << 6);

    float acc[4][4];
    #pragma unroll
    for (int i = 0; i < 4; i++)
        #pragma unroll
        for (int j = 0; j < 4; j++) acc[i][j] = 0.f;
    float ks = 0.f;

    for (int sl = 0; sl < 4; sl++) {
        #pragma unroll
        for (int i = 0; i < 8; i++) {
            int idx = tid + i * 256;            // 2048 elems
            int s = idx >> 6, d = idx & 63;
            Ks[s * 65 + d] = Kbase[((sl * 32 + s) << 6) + d];
            Vs[s * 65 + d] = Vbase[((sl * 32 + s) << 6) + d];
        }
        __syncthreads();
        #pragma unroll
        for (int s = 0; s < 32; s++) {
            float a[4], bb[4];
            #pragma unroll
            for (int i = 0; i < 4; i++) a[i] = Ks[s * 65 + ty * 4 + i];
            #pragma unroll
            for (int j = 0; j < 4; j++) bb[j] = Vs[s * 65 + tx * 4 + j];
            #pragma unroll
            for (int i = 0; i < 4; i++)
                #pragma unroll
                for (int j = 0; j < 4; j++) acc[i][j] += a[i] * bb[j];
        }
        if (tid < 64) {
            #pragma unroll
            for (int s = 0; s < 32; s++) ks += Ks[s * 65 + tid];
        }
        __syncthreads();
    }

    float* outp = g_stats + (h * NC + c) * STATS_STRIDE;
    #pragma unroll
    for (int i = 0; i < 4; i++)
        #pragma unroll
        for (int j = 0; j < 4; j++)
            outp[(ty * 4 + i) * 64 + tx * 4 + j] = acc[i][j];
    if (tid < 64) outp[4096 + tid] = ks;
}

// ---------------------------------------------------------------------------
// Kernel 3: exclusive prefix over chunks (per head).  grid=(H), 256 threads.
// ---------------------------------------------------------------------------
__global__ void prefix_kernel()
{
    const int h = blockIdx.x;
    for (int e = threadIdx.x; e < STATS_STRIDE; e += 256) {
        float run = 0.f;
        for (int c = 0; c < NC; c++) {
            g_pref [(h * NC + c) * STATS_STRIDE + e] = run;
            run +=  g_stats[(h * NC + c) * STATS_STRIDE + e];
        }
    }
}

// ---------------------------------------------------------------------------
// Kernel 4: per-(head,chunk) attention output.
//   num[t][j] = sum_i Qp[t][i]*Sprev[i][j] + sum_{s<=t} (Qp[t].Kp[s]) V[s][j]
//   den[t]    = max(Qp[t].zprev + rowsum_{s<=t} A[t][s], 1e-6)
// grid = (NC, H), 256 threads, dynamic smem ~179KB.
// ---------------------------------------------------------------------------
__global__ void __launch_bounds__(256, 1) attn_kernel()
{
    extern __shared__ float sm[];
    float* Qs   = sm;                    // 128*65
    float* Ks   = Qs + 128 * 65;         // 128*65
    float* Vs   = Ks + 128 * 65;         // 128*65
    float* Ss   = Vs + 128 * 65;         // 64*65
    float* zs   = Ss + 64 * 65;          // 64
    float* Am   = zs + 64;               // 128*129
    float* dens = Am + 128 * 129;        // 128

    const int c = blockIdx.x, h = blockIdx.y;
    const int tid = threadIdx.x;

    const float* Qbase = g_Qp + ((h * T + c * CH) << 6);
    const float* Kbase = g_Kp + ((h * T + c * CH) << 6);
    const float* Vbase = g_V  + ((h * T + c * CH) << 6);
    const float* P     = g_pref + (h * NC + c) * STATS_STRIDE;

    #pragma unroll
    for (int i = 0; i < 32; i++) {           // 8192 elems each
        int idx = tid + i * 256;
        int t = idx >> 6, d = idx & 63;
        Qs[t * 65 + d] = Qbase[idx];
        Ks[t * 65 + d] = Kbase[idx];
        Vs[t * 65 + d] = Vbase[idx];
    }
    #pragma unroll
    for (int i = 0; i < 16; i++) {           // Sprev 4096
        int idx = tid + i * 256;
        int r = idx >> 6, d = idx & 63;
        Ss[r * 65 + d] = P[idx];
    }
    if (tid < 64) zs[tid] = P[4096 + tid];
    __syncthreads();

    // Phase A: A[t][s] = (s<=t) ? Qp[t].Kp[s] : 0.   8x8 microtile.
    {
        const int ti = tid >> 4, tj = tid & 15;
        float a[8][8];
        #pragma unroll
        for (int i = 0; i < 8; i++)
            #pragma unroll
            for (int j = 0; j < 8; j++) a[i][j] = 0.f;
        for (int k = 0; k < 64; k++) {
            float qa[8], kb[8];
            #pragma unroll
            for (int i = 0; i < 8; i++) qa[i] = Qs[(ti * 8 + i) * 65 + k];
            #pragma unroll
            for (int j = 0; j < 8; j++) kb[j] = Ks[(tj * 8 + j) * 65 + k];
            #pragma unroll
            for (int i = 0; i < 8; i++)
                #pragma unroll
                for (int j = 0; j < 8; j++) a[i][j] += qa[i] * kb[j];
        }
        #pragma unroll
        for (int i = 0; i < 8; i++) {
            int t = ti * 8 + i;
            #pragma unroll
            for (int j = 0; j < 8; j++) {
                int s = tj * 8 + j;
                Am[t * 129 + s] = (s <= t) ? a[i][j] : 0.f;
            }
        }
    }
    __syncthreads();

    // den[t]
    if (tid < 128) {
        int t = tid;
        float d = 0.f;
        for (int i = 0; i < 64; i++) d += Qs[t * 65 + i] * zs[i];
        for (int s = 0; s < 128; s++) d += Am[t * 129 + s];
        dens[t] = fmaxf(d, 1e-6f);
    }
    __syncthreads();

    // Phase B: outputs 128x64, 8x4 microtile per thread.
    {
        const int ti = tid >> 4, tj = tid & 15;
        float acc[8][4];
        #pragma unroll
        for (int r = 0; r < 8; r++)
            #pragma unroll
            for (int j = 0; j < 4; j++) acc[r][j] = 0.f;

        for (int i = 0; i < 64; i++) {        // inter-chunk: Qp @ Sprev
            float q[8], s4[4];
            #pragma unroll
            for (int r = 0; r < 8; r++) q[r] = Qs[(ti * 8 + r) * 65 + i];
            #pragma unroll
            for (int j = 0; j < 4; j++) s4[j] = Ss[i * 65 + tj * 4 + j];
            #pragma unroll
            for (int r = 0; r < 8; r++)
                #pragma unroll
                for (int j = 0; j < 4; j++) acc[r][j] += q[r] * s4[j];
        }
        for (int s = 0; s < 128; s++) {       // intra-chunk: A @ V
            float a8[8], v4[4];
            #pragma unroll
            for (int r = 0; r < 8; r++) a8[r] = Am[(ti * 8 + r) * 129 + s];
            #pragma unroll
            for (int j = 0; j < 4; j++) v4[j] = Vs[s * 65 + tj * 4 + j];
            #pragma unroll
            for (int r = 0; r < 8; r++)
                #pragma unroll
                for (int j = 0; j < 4; j++) acc[r][j] += a8[r] * v4[j];
        }

        float* Ob = g_O + (c * CH) * Dm + h * DH;
        #pragma unroll
        for (int r = 0; r < 8; r++) {
            int t = ti * 8 + r;
            float inv = 1.f / dens[t];
            #pragma unroll
            for (int j = 0; j < 4; j++)
                Ob[t * Dm + tj * 4 + j] = acc[r][j] * inv;
        }
    }
}

// ---------------------------------------------------------------------------
// Kernel 5: output projection  y = g_O @ Wo + bo   (2048x512 @ 512x512)
// ---------------------------------------------------------------------------
__global__ void out_kernel(const float* __restrict__ Wo,
                           const float* __restrict__ bo,
                           float* __restrict__ y)
{
    __shared__ float As[64 * 16];
    __shared__ float Bs[16 * 64];

    const int row0 = blockIdx.x * 64;
    const int col0 = blockIdx.y * 64;
    const int tid = threadIdx.x;
    const int tx = tid & 15, ty = tid >> 4;

    float acc[4][4];
    #pragma unroll
    for (int i = 0; i < 4; i++)
        #pragma unroll
        for (int j = 0; j < 4; j++) acc[i][j] = 0.f;

    for (int k0 = 0; k0 < Dm; k0 += 16) {
        #pragma unroll
        for (int i = 0; i < 4; i++) {
            int idx = tid + i * 256;
            int r = idx >> 4, c = idx & 15;
            As[r * 16 + c] = g_O[(row0 + r) * Dm + k0 + c];
        }
        #pragma unroll
        for (int i = 0; i < 4; i++) {
            int idx = tid + i * 256;
            int r = idx >> 6, c = idx & 63;
            Bs[r * 64 + c] = Wo[(k0 + r) * Dm + col0 + c];
        }
        __syncthreads();
        #pragma unroll
        for (int k = 0; k < 16; k++) {
            float a[4], bb[4];
            #pragma unroll
            for (int i = 0; i < 4; i++) a[i] = As[(ty * 4 + i) * 16 + k];
            #pragma unroll
            for (int j = 0; j < 4; j++) bb[j] = Bs[k * 64 + tx * 4 + j];
            #pragma unroll
            for (int i = 0; i < 4; i++)
                #pragma unroll
                for (int j = 0; j < 4; j++) acc[i][j] += a[i] * bb[j];
        }
        __syncthreads();
    }

    #pragma unroll
    for (int i = 0; i < 4; i++) {
        int t = row0 + ty * 4 + i;
        #pragma unroll
        for (int j = 0; j < 4; j++) {
            int n = col0 + tx * 4 + j;
            y[t * Dm + n] = acc[i][j] + bo[n];
        }
    }
}

// ---------------------------------------------------------------------------
extern "C" void kernel_launch(void* const* d_in, const int* in_sizes, int n_in,
                              void* d_out, int out_size)
{
    const float* x  = (const float*)d_in[0];
    const float* Wq = (const float*)d_in[1];
    const float* bq = (const float*)d_in[2];
    const float* Wk = (const float*)d_in[3];
    const float* bk = (const float*)d_in[4];
    const float* Wv = (const float*)d_in[5];
    const float* bv = (const float*)d_in[6];
    const float* Wo = (const float*)d_in[7];
    const float* bo = (const float*)d_in[8];
    float* y = (float*)d_out;

    const int SMEM_ATTN = (128*65*3 + 64*65 + 64 + 128*129 + 128) * 4; // 183296 B
    cudaFuncSetAttribute(attn_kernel,
                         cudaFuncAttributeMaxDynamicSharedMemorySize, SMEM_ATTN);

    qkv_kernel  <<<dim3(T/64, H, 3), 256>>>(x, Wq, bq, Wk, bk, Wv, bv);
    chunk_kernel<<<dim3(NC, H), 256>>>();
    prefix_kernel<<<H, 256>>>();
    attn_kernel <<<dim3(NC, H), 256, SMEM_ATTN>>>();
    out_kernel  <<<dim3(T/64, H/*=Dm/64*/), 256>>>(Wo, bo, y);
}

// round 2
// speedup vs baseline: 1.1947x; 1.1947x over previous
#include <cuda_runtime.h>
#include <math.h>
#include <stdint.h>

// Problem constants
#define T   2048
#define Dm  512
#define H   8
#define DH  64
#define CH  128          // chunk length
#define NC  (T / CH)     // 16 chunks
#define STATS_STRIDE (DH*DH + DH)  // 4160 floats per (head,chunk): [KV 64x64 | ksum 64]

// Scratch (device globals — no allocation allowed)
__device__ float g_Qp[H * T * DH];
__device__ float g_Kp[H * T * DH];
__device__ float g_V [H * T * DH];
__device__ float g_stats[H * NC * STATS_STRIDE];
__device__ float g_pref [H * NC * STATS_STRIDE];
__device__ float g_O [T * Dm];

// ---------------------------------------------------------------------------
// TF32 tensor-core GEMM machinery (mma.sync.m16n8k8, 3-term split for ~fp32
// accuracy):  C += Ahi*Bhi + Alo*Bhi + Ahi*Blo
// Tile: BM=128, BN=64, BK=32. 256 threads = 8 warps (4 along M x 2 along N),
// warp tile 32x32 = 2 m-tiles x 4 n-tiles of m16n8.
// ---------------------------------------------------------------------------
#define PAD_A 44   // floats; (44*r + c) % 32 distinct for r in 0..7, c in 0..7; 16B-aligned rows
#define PAD_B 72   // floats; (72*k + n) % 32 distinct for k in 0..7, n in 0..7

__device__ __forceinline__ uint32_t f2tf32(float x) {
    uint32_t r;
    asm("cvt.rna.tf32.f32 %0, %1;" : "=r"(r) : "f"(x));
    return r;
}

__device__ __forceinline__ void mma8(float c[4], const uint32_t a[4], const uint32_t b[2]) {
    asm volatile(
        "mma.sync.aligned.m16n8k8.row.col.f32.tf32.tf32.f32 "
        "{%0,%1,%2,%3}, {%4,%5,%6,%7}, {%8,%9}, {%0,%1,%2,%3};"
        : "+f"(c[0]), "+f"(c[1]), "+f"(c[2]), "+f"(c[3])
        : "r"(a[0]), "r"(a[1]), "r"(a[2]), "r"(a[3]),
          "r"(b[0]), "r"(b[1]));
}

// Computes acc[2][4][4] = A[row0:row0+128, :] @ B[:, col0:col0+64]  (K = Dm = 512)
__device__ __forceinline__ void gemm_body(const float* __restrict__ A,
                                          const float* __restrict__ B,
                                          int row0, int col0,
                                          float acc[2][4][4],
                                          float* As, float* Bs)
{
    const int tid  = threadIdx.x;
    const int lane = tid & 31;
    const int wid  = tid >> 5;
    const int wm   = (wid & 3) * 32;   // warp row offset in tile
    const int wn   = (wid >> 2) * 32;  // warp col offset in tile

    #pragma unroll
    for (int mt = 0; mt < 2; mt++)
        #pragma unroll
        for (int nt = 0; nt < 4; nt++)
            #pragma unroll
            for (int i = 0; i < 4; i++) acc[mt][nt][i] = 0.f;

    const int lr = lane >> 2;   // 0..7
    const int lc = lane & 3;    // 0..3

    for (int k0 = 0; k0 < Dm; k0 += 32) {
        // stage A: 128 x 32 floats (1024 float4 slots)
        #pragma unroll
        for (int i = 0; i < 4; i++) {
            int slot = tid + i * 256;
            int r = slot >> 3, c4 = (slot & 7) << 2;
            float4 v = *(const float4*)&A[(row0 + r) * Dm + k0 + c4];
            *(float4*)&As[r * PAD_A + c4] = v;
        }
        // stage B: 32 x 64 floats (512 float4 slots)
        #pragma unroll
        for (int i = 0; i < 2; i++) {
            int slot = tid + i * 256;
            int r = slot >> 4, c4 = (slot & 15) << 2;
            float4 v = *(const float4*)&B[(k0 + r) * Dm + col0 + c4];
            *(float4*)&Bs[r * PAD_B + c4] = v;
        }
        __syncthreads();

        #pragma unroll
        for (int kk = 0; kk < 4; kk++) {
            const int kb = kk * 8;

            uint32_t ah[2][4], al[2][4];
            #pragma unroll
            for (int mt = 0; mt < 2; mt++) {
                int r = wm + mt * 16 + lr;
                int c = kb + lc;
                float f0 = As[r * PAD_A + c];
                float f1 = As[(r + 8) * PAD_A + c];
                float f2 = As[r * PAD_A + c + 4];
                float f3 = As[(r + 8) * PAD_A + c + 4];
                ah[mt][0] = f2tf32(f0); al[mt][0] = f2tf32(f0 - __uint_as_float(ah[mt][0]));
                ah[mt][1] = f2tf32(f1); al[mt][1] = f2tf32(f1 - __uint_as_float(ah[mt][1]));
                ah[mt][2] = f2tf32(f2); al[mt][2] = f2tf32(f2 - __uint_as_float(ah[mt][2]));
                ah[mt][3] = f2tf32(f3); al[mt][3] = f2tf32(f3 - __uint_as_float(ah[mt][3]));
            }

            uint32_t bh[4][2], bl[4][2];
            #pragma unroll
            for (int nt = 0; nt < 4; nt++) {
                int n  = wn + nt * 8 + lr;
                int kr = kb + lc;
                float g0 = Bs[kr * PAD_B + n];
                float g1 = Bs[(kr + 4) * PAD_B + n];
                bh[nt][0] = f2tf32(g0); bl[nt][0] = f2tf32(g0 - __uint_as_float(bh[nt][0]));
                bh[nt][1] = f2tf32(g1); bl[nt][1] = f2tf32(g1 - __uint_as_float(bh[nt][1]));
            }

            #pragma unroll
            for (int mt = 0; mt < 2; mt++)
                #pragma unroll
                for (int nt = 0; nt < 4; nt++) {
                    mma8(acc[mt][nt], ah[mt], bh[nt]);
                    mma8(acc[mt][nt], al[mt], bh[nt]);
                    mma8(acc[mt][nt], ah[mt], bl[nt]);
                }
        }
        __syncthreads();
    }
}

// ---------------------------------------------------------------------------
// Kernel 1: fused QKV projection via tf32 mma.
// grid = (T/128, 8, 3): blockIdx.y == head (BN=64 == head dim), z == which.
// Epilogue: Q,K -> elu(x)+1 ; V -> identity. Output [h][t][d] head-major.
// ---------------------------------------------------------------------------
__global__ void __launch_bounds__(256) qkv_mma_kernel(
    const float* __restrict__ x,
    const float* __restrict__ Wq, const float* __restrict__ bq,
    const float* __restrict__ Wk, const float* __restrict__ bk,
    const float* __restrict__ Wv, const float* __restrict__ bv)
{
    __shared__ float As[128 * PAD_A];
    __shared__ float Bs[32 * PAD_B];

    const int which = blockIdx.z;
    const float* W = (which == 0) ? Wq : (which == 1) ? Wk : Wv;
    const float* b = (which == 0) ? bq : (which == 1) ? bk : bv;
    float* out = (which == 0) ? g_Qp : (which == 1) ? g_Kp : g_V;

    const int row0 = blockIdx.x * 128;
    const int h    = blockIdx.y;
    const int col0 = h * 64;

    float acc[2][4][4];
    gemm_body(x, W, row0, col0, acc, As, Bs);

    const int lane = threadIdx.x & 31;
    const int wid  = threadIdx.x >> 5;
    const int wm   = (wid & 3) * 32;
    const int wn   = (wid >> 2) * 32;
    const int lr = lane >> 2, lc = lane & 3;

    #pragma unroll
    for (int mt = 0; mt < 2; mt++) {
        #pragma unroll
        for (int nt = 0; nt < 4; nt++) {
            int r = wm + mt * 16 + lr;
            int n = wn + nt * 8 + 2 * lc;
            #pragma unroll
            for (int i = 0; i < 4; i++) {
                int t = row0 + r + (i >= 2 ? 8 : 0);
                int d = n + (i & 1);
                float v = acc[mt][nt][i] + b[col0 + d];
                if (which < 2) v = (v > 0.f) ? (v + 1.f) : expf(v);  // elu+1
                out[((h * T + t) << 6) + d] = v;
            }
        }
    }
}

// ---------------------------------------------------------------------------
// Kernel 2: per-(head,chunk) stats: KV = Kp_chunk^T @ V_chunk, ksum.
// ---------------------------------------------------------------------------
__global__ void chunk_kernel()
{
    __shared__ float Ks[32 * 65];
    __shared__ float Vs[32 * 65];

    const int c = blockIdx.x, h = blockIdx.y;
    const int tid = threadIdx.x;
    const int tx = tid & 15, ty = tid >> 4;

    const float* Kbase = g_Kp + ((h * T + c * CH) << 6);
    const float* Vbase = g_V  + ((h * T + c * CH) << 6);

    float acc[4][4];
    #pragma unroll
    for (int i = 0; i < 4; i++)
        #pragma unroll
        for (int j = 0; j < 4; j++) acc[i][j] = 0.f;
    float ks = 0.f;

    for (int sl = 0; sl < 4; sl++) {
        #pragma unroll
        for (int i = 0; i < 8; i++) {
            int idx = tid + i * 256;
            int s = idx >> 6, d = idx & 63;
            Ks[s * 65 + d] = Kbase[((sl * 32 + s) << 6) + d];
            Vs[s * 65 + d] = Vbase[((sl * 32 + s) << 6) + d];
        }
        __syncthreads();
        #pragma unroll
        for (int s = 0; s < 32; s++) {
            float a[4], bb[4];
            #pragma unroll
            for (int i = 0; i < 4; i++) a[i] = Ks[s * 65 + ty * 4 + i];
            #pragma unroll
            for (int j = 0; j < 4; j++) bb[j] = Vs[s * 65 + tx * 4 + j];
            #pragma unroll
            for (int i = 0; i < 4; i++)
                #pragma unroll
                for (int j = 0; j < 4; j++) acc[i][j] += a[i] * bb[j];
        }
        if (tid < 64) {
            #pragma unroll
            for (int s = 0; s < 32; s++) ks += Ks[s * 65 + tid];
        }
        __syncthreads();
    }

    float* outp = g_stats + (h * NC + c) * STATS_STRIDE;
    #pragma unroll
    for (int i = 0; i < 4; i++)
        #pragma unroll
        for (int j = 0; j < 4; j++)
            outp[(ty * 4 + i) * 64 + tx * 4 + j] = acc[i][j];
    if (tid < 64) outp[4096 + tid] = ks;
}

// ---------------------------------------------------------------------------
// Kernel 3: exclusive prefix over chunks (per head).
// ---------------------------------------------------------------------------
__global__ void prefix_kernel()
{
    const int h = blockIdx.x;
    for (int e = threadIdx.x; e < STATS_STRIDE; e += 256) {
        float run = 0.f;
        for (int c = 0; c < NC; c++) {
            g_pref [(h * NC + c) * STATS_STRIDE + e] = run;
            run +=  g_stats[(h * NC + c) * STATS_STRIDE + e];
        }
    }
}

// ---------------------------------------------------------------------------
// Kernel 4: per-(head,chunk) attention output.
// ---------------------------------------------------------------------------
__global__ void __launch_bounds__(256, 1) attn_kernel()
{
    extern __shared__ float sm[];
    float* Qs   = sm;                    // 128*65
    float* Ks   = Qs + 128 * 65;         // 128*65
    float* Vs   = Ks + 128 * 65;         // 128*65
    float* Ss   = Vs + 128 * 65;         // 64*65
    float* zs   = Ss + 64 * 65;          // 64
    float* Am   = zs + 64;               // 128*129
    float* dens = Am + 128 * 129;        // 128

    const int c = blockIdx.x, h = blockIdx.y;
    const int tid = threadIdx.x;

    const float* Qbase = g_Qp + ((h * T + c * CH) << 6);
    const float* Kbase = g_Kp + ((h * T + c * CH) << 6);
    const float* Vbase = g_V  + ((h * T + c * CH) << 6);
    const float* P     = g_pref + (h * NC + c) * STATS_STRIDE;

    #pragma unroll
    for (int i = 0; i < 32; i++) {
        int idx = tid + i * 256;
        int t = idx >> 6, d = idx & 63;
        Qs[t * 65 + d] = Qbase[idx];
        Ks[t * 65 + d] = Kbase[idx];
        Vs[t * 65 + d] = Vbase[idx];
    }
    #pragma unroll
    for (int i = 0; i < 16; i++) {
        int idx = tid + i * 256;
        int r = idx >> 6, d = idx & 63;
        Ss[r * 65 + d] = P[idx];
    }
    if (tid < 64) zs[tid] = P[4096 + tid];
    __syncthreads();

    // Phase A: A[t][s] = (s<=t) ? Qp[t].Kp[s] : 0
    {
        const int ti = tid >> 4, tj = tid & 15;
        float a[8][8];
        #pragma unroll
        for (int i = 0; i < 8; i++)
            #pragma unroll
            for (int j = 0; j < 8; j++) a[i][j] = 0.f;
        for (int k = 0; k < 64; k++) {
            float qa[8], kb[8];
            #pragma unroll
            for (int i = 0; i < 8; i++) qa[i] = Qs[(ti * 8 + i) * 65 + k];
            #pragma unroll
            for (int j = 0; j < 8; j++) kb[j] = Ks[(tj * 8 + j) * 65 + k];
            #pragma unroll
            for (int i = 0; i < 8; i++)
                #pragma unroll
                for (int j = 0; j < 8; j++) a[i][j] += qa[i] * kb[j];
        }
        #pragma unroll
        for (int i = 0; i < 8; i++) {
            int t = ti * 8 + i;
            #pragma unroll
            for (int j = 0; j < 8; j++) {
                int s = tj * 8 + j;
                Am[t * 129 + s] = (s <= t) ? a[i][j] : 0.f;
            }
        }
    }
    __syncthreads();

    if (tid < 128) {
        int t = tid;
        float d = 0.f;
        for (int i = 0; i < 64; i++) d += Qs[t * 65 + i] * zs[i];
        for (int s = 0; s < 128; s++) d += Am[t * 129 + s];
        dens[t] = fmaxf(d, 1e-6f);
    }
    __syncthreads();

    // Phase B
    {
        const int ti = tid >> 4, tj = tid & 15;
        float acc[8][4];
        #pragma unroll
        for (int r = 0; r < 8; r++)
            #pragma unroll
            for (int j = 0; j < 4; j++) acc[r][j] = 0.f;

        for (int i = 0; i < 64; i++) {
            float q[8], s4[4];
            #pragma unroll
            for (int r = 0; r < 8; r++) q[r] = Qs[(ti * 8 + r) * 65 + i];
            #pragma unroll
            for (int j = 0; j < 4; j++) s4[j] = Ss[i * 65 + tj * 4 + j];
            #pragma unroll
            for (int r = 0; r < 8; r++)
                #pragma unroll
                for (int j = 0; j < 4; j++) acc[r][j] += q[r] * s4[j];
        }
        for (int s = 0; s < 128; s++) {
            float a8[8], v4[4];
            #pragma unroll
            for (int r = 0; r < 8; r++) a8[r] = Am[(ti * 8 + r) * 129 + s];
            #pragma unroll
            for (int j = 0; j < 4; j++) v4[j] = Vs[s * 65 + tj * 4 + j];
            #pragma unroll
            for (int r = 0; r < 8; r++)
                #pragma unroll
                for (int j = 0; j < 4; j++) acc[r][j] += a8[r] * v4[j];
        }

        float* Ob = g_O + (c * CH) * Dm + h * DH;
        #pragma unroll
        for (int r = 0; r < 8; r++) {
            int t = ti * 8 + r;
            float inv = 1.f / dens[t];
            #pragma unroll
            for (int j = 0; j < 4; j++)
                Ob[t * Dm + tj * 4 + j] = acc[r][j] * inv;
        }
    }
}

// ---------------------------------------------------------------------------
// Kernel 5: output projection via tf32 mma.  y = g_O @ Wo + bo
// grid = (T/128, Dm/64)
// ---------------------------------------------------------------------------
__global__ void __launch_bounds__(256) out_mma_kernel(
    const float* __restrict__ Wo,
    const float* __restrict__ bo,
    float* __restrict__ y)
{
    __shared__ float As[128 * PAD_A];
    __shared__ float Bs[32 * PAD_B];

    const int row0 = blockIdx.x * 128;
    const int col0 = blockIdx.y * 64;

    float acc[2][4][4];
    gemm_body(g_O, Wo, row0, col0, acc, As, Bs);

    const int lane = threadIdx.x & 31;
    const int wid  = threadIdx.x >> 5;
    const int wm   = (wid & 3) * 32;
    const int wn   = (wid >> 2) * 32;
    const int lr = lane >> 2, lc = lane & 3;

    #pragma unroll
    for (int mt = 0; mt < 2; mt++) {
        #pragma unroll
        for (int nt = 0; nt < 4; nt++) {
            int r = wm + mt * 16 + lr;
            int n = wn + nt * 8 + 2 * lc;
            #pragma unroll
            for (int i = 0; i < 4; i++) {
                int t = row0 + r + (i >= 2 ? 8 : 0);
                int d = col0 + n + (i & 1);
                y[t * Dm + d] = acc[mt][nt][i] + bo[d];
            }
        }
    }
}

// ---------------------------------------------------------------------------
extern "C" void kernel_launch(void* const* d_in, const int* in_sizes, int n_in,
                              void* d_out, int out_size)
{
    const float* x  = (const float*)d_in[0];
    const float* Wq = (const float*)d_in[1];
    const float* bq = (const float*)d_in[2];
    const float* Wk = (const float*)d_in[3];
    const float* bk = (const float*)d_in[4];
    const float* Wv = (const float*)d_in[5];
    const float* bv = (const float*)d_in[6];
    const float* Wo = (const float*)d_in[7];
    const float* bo = (const float*)d_in[8];
    float* y = (float*)d_out;

    const int SMEM_ATTN = (128*65*3 + 64*65 + 64 + 128*129 + 128) * 4; // 183296 B
    cudaFuncSetAttribute(attn_kernel,
                         cudaFuncAttributeMaxDynamicSharedMemorySize, SMEM_ATTN);

    qkv_mma_kernel<<<dim3(T/128, H, 3), 256>>>(x, Wq, bq, Wk, bk, Wv, bv);
    chunk_kernel  <<<dim3(NC, H), 256>>>();
    prefix_kernel <<<H, 256>>>();
    attn_kernel   <<<dim3(NC, H), 256, SMEM_ATTN>>>();
    out_mma_kernel<<<dim3(T/128, Dm/64), 256>>>(Wo, bo, y);
}